// round 12
// baseline (speedup 1.0000x reference)
#include <cuda_runtime.h>
#include <cstddef>

// HBV fused time-scan. Key change R10: 256-thread blocks -> 40 CTAs -> 8 warps/SM
// = 2 warps per SMSP, so HARDWARE warp interleaving fills dependency stalls
// (single-warp fma pipe rt=2 + 56cyc soil chain was the R6 limiter at 180cyc/step).
// Plus: merged melt/refreeze, refactored routing, imm-offset addressing.

#define NSTEP 730
#define NGRID 10000
#define PFD   10
#define ROWX  (NGRID*3)
#define NEARZERO 1e-5f

__device__ __forceinline__ float fast_exp2(float v) {
    float r;
    asm("ex2.approx.ftz.f32 %0, %1;" : "=f"(r) : "f"(v));
    return r;   // MUFU.EX2
}

__global__ __launch_bounds__(256, 1)
void hbv_kernel(const float* __restrict__ x,
                const float* __restrict__ params,
                float* __restrict__ out)
{
    const int cell = blockIdx.x * blockDim.x + threadIdx.x;
    if (cell >= NGRID) return;

    const float* p = params + ((size_t)(NSTEP - 1) * NGRID + (size_t)cell) * 12;
    const float BETA    = 1.0f   + p[0]  * 5.0f;
    const float FC      = 50.0f  + p[1]  * 950.0f;
    const float K0      = 0.05f  + p[2]  * 0.85f;
    const float K1      = 0.01f  + p[3]  * 0.49f;
    const float K2      = 0.001f + p[4]  * 0.199f;
    const float LP      = 0.2f   + p[5]  * 0.8f;
    const float PERCmax =          p[6]  * 10.0f;
    const float UZL     =          p[7]  * 100.0f;
    const float TT      = -2.5f  + p[8]  * 5.0f;
    const float CFMAX   = 0.5f   + p[9]  * 9.5f;
    const float CFR     =          p[10] * 0.1f;
    const float CWH     =          p[11] * 0.2f;

    const float invLPFC     = 1.0f / (LP * FC);
    const float betaLgInvFC = BETA * __log2f(1.0f / FC);   // (SM/FC)^B = exp2(B*lg SM + this)
    const float K1m         = 1.0f - K1;
    const float K01         = K0 * K1m;                    // Q0+Q1 = K01*u + K1*s1

    float SNOWPACK = 0.001f, MELTWATER = 0.001f, SM = 0.001f;
    float SUZ = 0.001f, SLZ = 0.001f;

    const size_t n = (size_t)NSTEP * NGRID;
    // bases chosen so body j of the current chunk uses compile-time offset j*NGRID
    float* __restrict__ qp = out + cell - NGRID;            // routing (trails 1 step)
    float* __restrict__ ap = out + n + cell - NGRID;
    float* __restrict__ sp = out + 2 * n + cell + NGRID;    // snow (leads 1 step)
    const float* __restrict__ xb = x + (size_t)cell * 3;    // row 10*c at chunk c entry

    float rt_c, c1_c, PET_c, rt_n, c1_n, PET_n;             // snow->soil staging
    float rech_s = 0.0f, exc_s = 0.0f, ET_s = 0.0f;         // soil->routing staging

    float bP[PFD], bT[PFD], bE[PFD];    // current chunk snow inputs
    float nP[PFD], nT[PFD], nE[PFD];    // next chunk (prefetch)

    // ---- stage macros ----
#define SNOW(Pt_, Tt_, Et_, SOFF)                                            \
    {                                                                        \
        const float Pt = (Pt_), Tt = (Tt_), Et = (Et_);                      \
        const float RAIN = (Tt >= TT) ? Pt : 0.0f;                           \
        const float m    = CFMAX * (Tt - TT);                                \
        const float sel  = (m >= 0.0f) ? m : (CFR * m);    /* melt or -refr */ \
        const float SP1  = SNOWPACK + (Pt - RAIN);                           \
        const float nn   = fminf(fmaxf(sel, -MELTWATER), SP1);               \
        SNOWPACK  = SP1 - nn;                                                \
        MELTWATER = MELTWATER + nn;                                          \
        const float tosoil = fmaxf(fmaf(-CWH, SNOWPACK, MELTWATER), 0.0f);   \
        MELTWATER -= tosoil;                                                 \
        rt_n  = RAIN + tosoil;                                               \
        c1_n  = Et * invLPFC;                                                \
        PET_n = Et;                                                          \
        sp[(SOFF)] = SNOWPACK;                                               \
    }

#define ROUT(MOFF)                                                           \
    {                                                                        \
        const float SUZa = SUZ + rech_s + exc_s;                             \
        const float PERC = fminf(SUZa, PERCmax);                             \
        const float s1   = SUZa - PERC;                                      \
        const float u    = fmaxf(s1 - UZL, 0.0f);                            \
        const float t1   = K01 * u;                                          \
        const float Q01  = fmaf(K1, s1, t1);                                 \
        SUZ = fmaf(K1m, s1, -t1);                                            \
        SLZ += PERC;                                                         \
        const float Q2 = K2 * SLZ;                                           \
        SLZ -= Q2;                                                           \
        qp[(MOFF)] = Q01 + Q2;                                               \
        ap[(MOFF)] = ET_s;                                                   \
    }

#define NOOP {}

#define STEP(SNOWP, ROUTP)                                                   \
    {                                                                        \
        const float lg = __log2f(SM);                                        \
        const float sw = fast_exp2(fmaf(BETA, lg, betaLgInvFC));             \
        ROUTP;                                                               \
        SNOWP;                                                               \
        const float a   = SM + rt_c;                                         \
        const float SMn = fmaxf(fmaf(-rt_c, sw, a), SM);   /* min(sw,1) folded */ \
        rech_s = a - SMn;                                                    \
        exc_s  = fmaxf(SMn - FC, 0.0f);                                      \
        ET_s   = fminf(fminf(SMn * c1_c, PET_c), SMn);                       \
        SM = fmaxf(fmaxf(fmaf(-c1_c, SMn, SMn), SMn - PET_c), NEARZERO);     \
        rt_c = rt_n; c1_c = c1_n; PET_c = PET_n;                             \
    }

    // prefetch next chunk's snow-input rows (rows xb+11 .. xb+20)
#define PREF()                                                               \
    {                                                                        \
        _Pragma("unroll")                                                    \
        for (int j = 0; j < PFD; ++j) {                                      \
            nP[j] = xb[(11 + j) * ROWX];                                     \
            nT[j] = xb[(11 + j) * ROWX + 1];                                 \
            nE[j] = xb[(11 + j) * ROWX + 2];                                 \
        }                                                                    \
    }

#define ROTATE()                                                             \
    {                                                                        \
        _Pragma("unroll")                                                    \
        for (int j = 0; j < PFD; ++j) { bP[j]=nP[j]; bT[j]=nT[j]; bE[j]=nE[j]; } \
    }

#define ADVANCE()                                                            \
    { qp += PFD * NGRID; ap += PFD * NGRID; sp += PFD * NGRID; xb += PFD * ROWX; }

#define CONSUME_FULL()                                                       \
    {                                                                        \
        _Pragma("unroll")                                                    \
        for (int j = 0; j < PFD; ++j)                                        \
            STEP(SNOW(bP[j], bT[j], bE[j], j * NGRID), ROUT(j * NGRID));     \
    }

    // ---- prologue ----
    const float P0 = xb[0], T0 = xb[1], E0 = xb[2];        // row 0
#pragma unroll
    for (int j = 0; j < PFD; ++j) {                        // chunk 0: rows 1..10
        bP[j] = xb[(1 + j) * ROWX];
        bT[j] = xb[(1 + j) * ROWX + 1];
        bE[j] = xb[(1 + j) * ROWX + 2];
    }
    PREF();                                                // chunk 1: rows 11..20

    SNOW(P0, T0, E0, -NGRID);                              // step 0 (SWE row 0)
    rt_c = rt_n; c1_c = c1_n; PET_c = PET_n;

    // ---- chunk 0: body 0 has no routing ----
    STEP(SNOW(bP[0], bT[0], bE[0], 0), NOOP);
#pragma unroll
    for (int j = 1; j < PFD; ++j)
        STEP(SNOW(bP[j], bT[j], bE[j], j * NGRID), ROUT(j * NGRID));
    ROTATE();
    ADVANCE();

    // ---- chunks 1..70: steady state ----
    for (int c = 1; c <= 70; ++c) {
        PREF();
        CONSUME_FULL();
        ROTATE();
        ADVANCE();
    }

    // ---- chunk 71: prefetch chunk 72 with clamped last row (730 -> 729) ----
    {
#pragma unroll
        for (int j = 0; j < PFD - 1; ++j) {
            nP[j] = xb[(11 + j) * ROWX];
            nT[j] = xb[(11 + j) * ROWX + 1];
            nE[j] = xb[(11 + j) * ROWX + 2];
        }
        nP[PFD - 1] = xb[(11 + PFD - 2) * ROWX];           // dup row 729 (unused)
        nT[PFD - 1] = xb[(11 + PFD - 2) * ROWX + 1];
        nE[PFD - 1] = xb[(11 + PFD - 2) * ROWX + 2];
    }
    CONSUME_FULL();
    ROTATE();
    ADVANCE();

    // ---- chunk 72: bodies 0..8 full, body 9 (step 729) without snow ----
#pragma unroll
    for (int j = 0; j < PFD - 1; ++j)
        STEP(SNOW(bP[j], bT[j], bE[j], j * NGRID), ROUT(j * NGRID));
    STEP(NOOP, ROUT((PFD - 1) * NGRID));

    // ---- epilogue: routing for step 729 ----
    ROUT(PFD * NGRID);
}

extern "C" void kernel_launch(void* const* d_in, const int* in_sizes, int n_in,
                              void* d_out, int out_size)
{
    const float* x      = (const float*)d_in[0];
    const float* params = (const float*)d_in[1];
    float* out          = (float*)d_out;

    const int threads = 256;
    const int blocks  = (NGRID + threads - 1) / threads;   // 40 -> 2 warps/SMSP
    hbv_kernel<<<blocks, threads>>>(x, params, out);
}

// round 13
// speedup vs baseline: 1.3448x; 1.3448x over previous
#include <cuda_runtime.h>
#include <cstddef>

// HBV fused time-scan — WARP-SPECIALIZED producer/consumer.
// Block = 256 threads on 79 SMs: warps 0-3 ("front": snow+soil+MUFU chain) and
// warps 4-7 ("back": routing + Q/AET stores) handle the SAME 128 cells.
// wid%4 puts 1 front + 1 back warp on EVERY SMSP -> back fills front's
// dependency stalls (R10 showed 1.44x per-SMSP from pairing) while keeping
// R6's 79-SM spread. Handoff: (rech+excess, ET) via double-buffered SMEM,
// one __syncthreads per 10-step chunk.

#define NSTEP 730
#define NGRID 10000
#define PFD   10
#define ROWX  (NGRID*3)
#define NEARZERO 1e-5f

__device__ __forceinline__ float fast_exp2(float v) {
    float r;
    asm("ex2.approx.ftz.f32 %0, %1;" : "=f"(r) : "f"(v));
    return r;   // MUFU.EX2
}

__global__ __launch_bounds__(256, 1)
void hbv_kernel(const float* __restrict__ x,
                const float* __restrict__ params,
                float* __restrict__ out)
{
    const int  tid   = threadIdx.x;
    const int  wid   = tid >> 5;
    const bool front = (wid < 4);
    const int  l     = tid & 127;                 // cell slot within CTA
    const int  cell  = blockIdx.x * 128 + l;
    const bool valid = (cell < NGRID);
    const int  cellc = valid ? cell : (NGRID - 1);

    // [buf][step][field][cell] : field 0 = rech+excess, field 1 = ET
    __shared__ float smbuf[2][PFD][2][128];

    const float* p = params + ((size_t)(NSTEP - 1) * NGRID + (size_t)cellc) * 12;
    const float BETA    = 1.0f   + p[0]  * 5.0f;
    const float FC      = 50.0f  + p[1]  * 950.0f;
    const float K0      = 0.05f  + p[2]  * 0.85f;
    const float K1      = 0.01f  + p[3]  * 0.49f;
    const float K2      = 0.001f + p[4]  * 0.199f;
    const float LP      = 0.2f   + p[5]  * 0.8f;
    const float PERCmax =          p[6]  * 10.0f;
    const float UZL     =          p[7]  * 100.0f;
    const float TT      = -2.5f  + p[8]  * 5.0f;
    const float CFMAX   = 0.5f   + p[9]  * 9.5f;
    const float CFR     =          p[10] * 0.1f;
    const float CWH     =          p[11] * 0.2f;

    const float invLPFC     = 1.0f / (LP * FC);
    const float betaLgInvFC = BETA * __log2f(1.0f / FC);
    const float K1m         = 1.0f - K1;
    const float K01         = K0 * K1m;          // Q0+Q1 = K01*u + K1*s1

    const size_t n = (size_t)NSTEP * NGRID;

    // ---- front state ----
    float SNOWPACK = 0.001f, MELTWATER = 0.001f, SM = 0.001f;
    float rt_c, c1_c, PET_c, rt_n, c1_n, PET_n;
    float bP[PFD], bT[PFD], bE[PFD], nP[PFD], nT[PFD], nE[PFD];
    const float* xb = x + (size_t)cellc * 3;
    float* sp = out + 2 * n + cellc + NGRID;     // SWE (snow leads 1 step)

    // ---- back state ----
    float SUZ = 0.001f, SLZ = 0.001f;
    float* qp = out + cellc;                      // Qsim
    float* ap = out + n + cellc;                  // AET

    // ================= front macros =================
#define SNOWM(Pt_, Tt_, Et_, SOFF)                                           \
    {                                                                        \
        const float Pt = (Pt_), Tt = (Tt_), Et = (Et_);                      \
        const float RAIN = (Tt >= TT) ? Pt : 0.0f;                           \
        const float m    = CFMAX * (Tt - TT);                                \
        const float sel  = (m >= 0.0f) ? m : (CFR * m);                      \
        const float SP1  = SNOWPACK + (Pt - RAIN);                           \
        const float nn   = fminf(fmaxf(sel, -MELTWATER), SP1);               \
        SNOWPACK  = SP1 - nn;                                                \
        MELTWATER = MELTWATER + nn;                                          \
        const float tosoil = fmaxf(fmaf(-CWH, SNOWPACK, MELTWATER), 0.0f);   \
        MELTWATER -= tosoil;                                                 \
        rt_n  = RAIN + tosoil;                                               \
        c1_n  = Et * invLPFC;                                                \
        PET_n = Et;                                                          \
        if (valid) sp[(SOFF)] = SNOWPACK;                                    \
    }

#define NOOP {}

#define STEPF(SNOWP, J, BUF)                                                 \
    {                                                                        \
        const float lg = __log2f(SM);                                        \
        const float sw = fast_exp2(fmaf(BETA, lg, betaLgInvFC));             \
        SNOWP;                                                               \
        const float a   = SM + rt_c;                                         \
        const float SMn = fmaxf(fmaf(-rt_c, sw, a), SM);                     \
        const float rex = (a - SMn) + fmaxf(SMn - FC, 0.0f);                 \
        const float ET  = fminf(fminf(SMn * c1_c, PET_c), SMn);              \
        SM = fmaxf(fmaxf(fmaf(-c1_c, SMn, SMn), SMn - PET_c), NEARZERO);     \
        smbuf[(BUF)][(J)][0][l] = rex;                                       \
        smbuf[(BUF)][(J)][1][l] = ET;                                        \
        rt_c = rt_n; c1_c = c1_n; PET_c = PET_n;                             \
    }

#define PREF()                                                               \
    {                                                                        \
        _Pragma("unroll")                                                    \
        for (int j = 0; j < PFD; ++j) {                                      \
            nP[j] = xb[(11 + j) * ROWX];                                     \
            nT[j] = xb[(11 + j) * ROWX + 1];                                 \
            nE[j] = xb[(11 + j) * ROWX + 2];                                 \
        }                                                                    \
    }

#define ROTATE()                                                             \
    {                                                                        \
        _Pragma("unroll")                                                    \
        for (int j = 0; j < PFD; ++j) { bP[j]=nP[j]; bT[j]=nT[j]; bE[j]=nE[j]; } \
    }

#define ADV_F() { xb += PFD * ROWX; sp += PFD * NGRID; }

#define FILL_BODIES(BUF)                                                     \
    {                                                                        \
        _Pragma("unroll")                                                    \
        for (int j = 0; j < PFD; ++j)                                        \
            STEPF(SNOWM(bP[j], bT[j], bE[j], j * NGRID), j, BUF);            \
    }

    // ================= back macro =================
#define CONSUME(BUF)                                                         \
    {                                                                        \
        _Pragma("unroll")                                                    \
        for (int j = 0; j < PFD; ++j) {                                      \
            const float rex = smbuf[(BUF)][j][0][l];                         \
            const float ET  = smbuf[(BUF)][j][1][l];                         \
            const float SUZa = SUZ + rex;                                    \
            const float PERC = fminf(SUZa, PERCmax);                         \
            const float s1   = SUZa - PERC;                                  \
            const float u    = fmaxf(s1 - UZL, 0.0f);                        \
            const float t1   = K01 * u;                                      \
            const float Q01  = fmaf(K1, s1, t1);                             \
            SUZ = fmaf(K1m, s1, -t1);                                        \
            SLZ += PERC;                                                     \
            const float Q2 = K2 * SLZ;                                       \
            SLZ -= Q2;                                                       \
            if (valid) { qp[j * NGRID] = Q01 + Q2; ap[j * NGRID] = ET; }     \
        }                                                                    \
        qp += PFD * NGRID; ap += PFD * NGRID;                                \
    }

    // ================= pipeline =================
    if (front) {
        // prologue: step-0 inputs + chunk 0 (rows 1..10) + prefetch chunk 1
        const float P0 = xb[0], T0 = xb[1], E0 = xb[2];
#pragma unroll
        for (int j = 0; j < PFD; ++j) {
            bP[j] = xb[(1 + j) * ROWX];
            bT[j] = xb[(1 + j) * ROWX + 1];
            bE[j] = xb[(1 + j) * ROWX + 2];
        }
        PREF();                                   // chunk 1 inputs (rows 11..20)
        SNOWM(P0, T0, E0, -NGRID);                // snow(0), SWE row 0
        rt_c = rt_n; c1_c = c1_n; PET_c = PET_n;
        FILL_BODIES(0);                           // chunk 0 -> buf 0
        ROTATE(); ADV_F();
    }
    __syncthreads();

    // epochs c=0..69: front fills chunk c+1 (plain prefetch of chunk c+2),
    //                 back consumes chunk c
    for (int c = 0; c <= 69; ++c) {
        if (front) {
            PREF();                               // chunk c+2 (max row 720, safe)
            if ((c & 1) == 0) { FILL_BODIES(1); } else { FILL_BODIES(0); }
            ROTATE(); ADV_F();
        } else {
            if ((c & 1) == 0) { CONSUME(0); } else { CONSUME(1); }
        }
        __syncthreads();
    }

    // epoch c=70: front fills chunk 71, prefetch chunk 72 with clamped last row
    if (front) {
#pragma unroll
        for (int j = 0; j < PFD - 1; ++j) {
            nP[j] = xb[(11 + j) * ROWX];
            nT[j] = xb[(11 + j) * ROWX + 1];
            nE[j] = xb[(11 + j) * ROWX + 2];
        }
        nP[PFD-1] = xb[(11 + PFD - 2) * ROWX];    // dup row 729 (unused)
        nT[PFD-1] = xb[(11 + PFD - 2) * ROWX + 1];
        nE[PFD-1] = xb[(11 + PFD - 2) * ROWX + 2];
        FILL_BODIES(1);                           // chunk 71 -> buf 1
        ROTATE(); ADV_F();
    } else {
        CONSUME(0);                               // chunk 70
    }
    __syncthreads();

    // epoch c=71: front fills chunk 72 (last body: no snow), back consumes 71
    if (front) {
#pragma unroll
        for (int j = 0; j < PFD - 1; ++j)
            STEPF(SNOWM(bP[j], bT[j], bE[j], j * NGRID), j, 0);
        STEPF(NOOP, PFD - 1, 0);                  // step 729
    } else {
        CONSUME(1);                               // chunk 71
    }
    __syncthreads();

    // final: back consumes chunk 72
    if (!front) {
        CONSUME(0);
    }
}

extern "C" void kernel_launch(void* const* d_in, const int* in_sizes, int n_in,
                              void* d_out, int out_size)
{
    const float* x      = (const float*)d_in[0];
    const float* params = (const float*)d_in[1];
    float* out          = (float*)d_out;

    const int blocks = (NGRID + 127) / 128;       // 79 CTAs, 256 thr each
    hbv_kernel<<<blocks, 256>>>(x, params, out);
}